// round 15
// baseline (speedup 1.0000x reference)
#include <cuda_runtime.h>
#include <cuda_bf16.h>
#include <cstdint>

#define NN 100000
#define NPAD 100096              // 1564 * 64
#define EE 800000
#define DD 128

// ---------------- static device scratch (no allocations allowed) ----------------
__device__ float g_h0[NPAD * DD];             // hidden features ping
__device__ float g_h1[NPAD * DD];             // hidden features pong
__device__ __nv_bfloat16 g_WThi[3 * DD * DD]; // per-layer W^T [n][k] bf16 hi
__device__ __nv_bfloat16 g_WTlo[3 * DD * DD]; // residuals
__device__ int   g_deg_out[NN];
__device__ int   g_deg_in[NN];
__device__ float g_norm_out[NN];
__device__ float g_norm_in[NN];
__device__ int   g_row_ptr[NN + 1];           // CSR by dst
__device__ int   g_fill[NN];
__device__ int   g_col[EE];                   // src index per CSR slot
__device__ int   g_part[256];                 // scan partials
__device__ float g_colsum[DD];                // column sums of final h (for mean)

// ---------------- small helpers ----------------
__device__ __forceinline__ void f4_fma(float4& acc, float4 v, float s) {
    acc.x = fmaf(v.x, s, acc.x);
    acc.y = fmaf(v.y, s, acc.y);
    acc.z = fmaf(v.z, s, acc.z);
    acc.w = fmaf(v.w, s, acc.w);
}
__device__ __forceinline__ float4 f4_add(float4 a, float4 b) {
    return make_float4(a.x + b.x, a.y + b.y, a.z + b.z, a.w + b.w);
}
__device__ __forceinline__ uint32_t smem_u32(const void* p) {
    uint32_t a;
    asm("{ .reg .u64 t; cvta.to.shared.u64 t, %1; cvt.u32.u64 %0, t; }" : "=r"(a) : "l"(p));
    return a;
}
__device__ __forceinline__ uint32_t pack_bf2(float x, float y) {
    __nv_bfloat162 t;
    t.x = __float2bfloat16(x);
    t.y = __float2bfloat16(y);
    return *(uint32_t*)&t;
}

// ---------------- sm_80-era tensor ops (valid on plain sm_100 target) ----------
#define LDSM4(r0, r1, r2, r3, addr) \
    asm volatile("ldmatrix.sync.aligned.m8n8.x4.shared.b16 {%0,%1,%2,%3}, [%4];" \
                 : "=r"(r0), "=r"(r1), "=r"(r2), "=r"(r3) : "r"(addr))
#define LDSM2(r0, r1, addr) \
    asm volatile("ldmatrix.sync.aligned.m8n8.x2.shared.b16 {%0,%1}, [%2];" \
                 : "=r"(r0), "=r"(r1) : "r"(addr))
#define MMA16816(c, a0, a1, a2, a3, b0, b1) \
    asm volatile("mma.sync.aligned.m16n8k16.row.col.f32.bf16.bf16.f32 " \
                 "{%0,%1,%2,%3}, {%4,%5,%6,%7}, {%8,%9}, {%0,%1,%2,%3};" \
                 : "+f"((c)[0]), "+f"((c)[1]), "+f"((c)[2]), "+f"((c)[3]) \
                 : "r"(a0), "r"(a1), "r"(a2), "r"(a3), "r"(b0), "r"(b1))

// swizzled offset inside a tile with 256B rows (128 bf16/row), 16B units:
// off = r*256 + ((c16 ^ (r&7))*16) -> ldmatrix 8-row groups hit distinct banks
__device__ __forceinline__ uint32_t tile_off(int r, int c16) {
    return ((uint32_t)r << 8) + (((uint32_t)(c16 ^ (r & 7))) << 4);
}

// ---------------- preprocessing kernels ----------------
__global__ void k_zero(int n) {
    int i = blockIdx.x * blockDim.x + threadIdx.x;
    if (i < n) { g_deg_out[i] = 0; g_deg_in[i] = 0; g_fill[i] = 0; }
    if (i < DD) g_colsum[i] = 0.0f;
}

__global__ void k_degrees(const int* __restrict__ src, const int* __restrict__ dst, int e) {
    int i = blockIdx.x * blockDim.x + threadIdx.x;
    if (i < e) {
        atomicAdd(&g_deg_out[src[i]], 1);
        atomicAdd(&g_deg_in[dst[i]], 1);
    }
}

__global__ void k_norms(int n) {
    int i = blockIdx.x * blockDim.x + threadIdx.x;
    if (i < n) {
        g_norm_out[i] = rsqrtf(fmaxf((float)g_deg_out[i], 1.0f));
        g_norm_in[i]  = rsqrtf(fmaxf((float)g_deg_in[i], 1.0f));
    }
}

__global__ void k_scan_partial(int n) {
    int idx = blockIdx.x * 1024 + threadIdx.x;
    int v = (idx < n) ? g_deg_in[idx] : 0;
    #pragma unroll
    for (int o = 16; o > 0; o >>= 1) v += __shfl_down_sync(0xFFFFFFFFu, v, o);
    __shared__ int ws[32];
    if ((threadIdx.x & 31) == 0) ws[threadIdx.x >> 5] = v;
    __syncthreads();
    if (threadIdx.x < 32) {
        int s = ws[threadIdx.x];
        #pragma unroll
        for (int o = 16; o > 0; o >>= 1) s += __shfl_down_sync(0xFFFFFFFFu, s, o);
        if (threadIdx.x == 0) g_part[blockIdx.x] = s;
    }
}

__global__ void k_scan_mid(int nchunk, int n) {
    int sum = 0;
    for (int i = 0; i < nchunk; i++) {
        int v = g_part[i];
        g_part[i] = sum;
        sum += v;
    }
    g_row_ptr[n] = sum;  // == E
}

__global__ void k_scan_final(int n) {
    int idx = blockIdx.x * 1024 + threadIdx.x;
    int v = (idx < n) ? g_deg_in[idx] : 0;
    int lane = threadIdx.x & 31, wid = threadIdx.x >> 5;
    int inc = v;
    #pragma unroll
    for (int o = 1; o < 32; o <<= 1) {
        int t = __shfl_up_sync(0xFFFFFFFFu, inc, o);
        if (lane >= o) inc += t;
    }
    __shared__ int ws[32];
    if (lane == 31) ws[wid] = inc;
    __syncthreads();
    if (wid == 0) {
        int s = ws[lane];
        #pragma unroll
        for (int o = 1; o < 32; o <<= 1) {
            int t = __shfl_up_sync(0xFFFFFFFFu, s, o);
            if (lane >= o) s += t;
        }
        ws[lane] = s;
    }
    __syncthreads();
    int add = (wid > 0) ? ws[wid - 1] : 0;
    if (idx < n) g_row_ptr[idx] = (inc - v) + add + g_part[blockIdx.x];
}

__global__ void k_csr_fill(const int* __restrict__ src, const int* __restrict__ dst, int e) {
    int i = blockIdx.x * blockDim.x + threadIdx.x;
    if (i < e) {
        int d = dst[i];
        int pos = g_row_ptr[d] + atomicAdd(&g_fill[d], 1);
        g_col[pos] = src[i];
    }
}

// W split+transpose: fp32 W[k][n] -> bf16 hi/lo W^T[n][k]
__global__ void k_split_w(const float* __restrict__ W, int lay) {
    int i = blockIdx.x * blockDim.x + threadIdx.x;
    if (i >= DD * DD) return;
    int k = i / DD, n = i % DD;
    float w = W[i];
    __nv_bfloat16 hi = __float2bfloat16(w);
    __nv_bfloat16 lo = __float2bfloat16(w - __bfloat162float(hi));
    size_t o = (size_t)lay * DD * DD + (size_t)n * DD + k;
    g_WThi[o] = hi;
    g_WTlo[o] = lo;
}

// ---------------- fused layer: gather-aggregate + bf16-split GEMM --------------
// 64-row tile, 256 threads (8 warps), 96KB smem -> 2 CTAs/SM so one CTA's
// L2-bound gather overlaps the other's MMA.
// R13 bug fixed: hidden features are DOUBLE-BUFFERED (g_h0/g_h1) so the gather
// of layer k never reads the buffer layer k is writing (cross-block race).
// Phase 1: warp-per-node gather (fp32 regs) -> split -> swizzled smem A tiles.
// Phase 2: ldmatrix + mma.sync, D = Ah·Wh + Al·Wh + Ah·Wl (fp32 acc).
#define SM_AH 0          // 64x128 bf16 = 16KB
#define SM_AL 16384
#define SM_WH 32768      // 128x128 bf16 = 32KB
#define SM_WL 65536
#define SM_TOT 98304

__global__ void __launch_bounds__(256, 2) k_layer(
    const float4* __restrict__ in, int lay,
    const float* __restrict__ bias, float* __restrict__ out, int last, int M)
{
    extern __shared__ __align__(16) char smem[];
    uint32_t sb = smem_u32(smem);
    int tid = threadIdx.x;
    int wid = tid >> 5, lane = tid & 31;
    int row0 = blockIdx.x * 64;

    // src/dst buffers derived from layer index (ping-pong; no same-launch aliasing)
    const float4* __restrict__ feat4 =
        (lay == 0) ? in : (lay == 1 ? (const float4*)g_h0 : (const float4*)g_h1);
    float* __restrict__ dst = last ? out : (lay == 0 ? g_h0 : g_h1);

    // ---- stage W hi/lo tiles (each thread 8 x 16B per tile) ----
    {
        const __nv_bfloat16* __restrict__ wh = g_WThi + (size_t)lay * DD * DD;
        const __nv_bfloat16* __restrict__ wl = g_WTlo + (size_t)lay * DD * DD;
        #pragma unroll
        for (int t = 0; t < 8; t++) {
            int i = tid + t * 256;           // 0..2047
            int r = i >> 4, c16 = i & 15;
            uint32_t off = tile_off(r, c16);
            size_t gw = (size_t)r * DD + c16 * 8;
            *(uint4*)(smem + SM_WH + off) = *(const uint4*)(wh + gw);
            *(uint4*)(smem + SM_WL + off) = *(const uint4*)(wl + gw);
        }
    }

    // ---- gather-aggregate 8 rows per warp into smem A tiles ----
    {
        uint32_t a_off_col = (uint32_t)(lane >> 1);   // c16
        #pragma unroll
        for (int q = 0; q < 8; q++) {
            int lr = wid * 8 + q;
            int node = row0 + lr;
            float4 acc = make_float4(0.f, 0.f, 0.f, 0.f);
            float ni = 0.0f;
            if (node < M) {
                ni = g_norm_in[node];
                int beg = g_row_ptr[node];
                int end = g_row_ptr[node + 1];
                int e = beg;
                for (; e + 4 <= end; e += 4) {
                    int s0 = g_col[e], s1 = g_col[e + 1], s2 = g_col[e + 2], s3 = g_col[e + 3];
                    float n0 = g_norm_out[s0], n1 = g_norm_out[s1];
                    float n2 = g_norm_out[s2], n3 = g_norm_out[s3];
                    float4 v0 = feat4[(size_t)s0 * 32 + lane];
                    float4 v1 = feat4[(size_t)s1 * 32 + lane];
                    float4 v2 = feat4[(size_t)s2 * 32 + lane];
                    float4 v3 = feat4[(size_t)s3 * 32 + lane];
                    f4_fma(acc, v0, n0);
                    f4_fma(acc, v1, n1);
                    f4_fma(acc, v2, n2);
                    f4_fma(acc, v3, n3);
                }
                for (; e < end; e++) {
                    int s = g_col[e];
                    f4_fma(acc, feat4[(size_t)s * 32 + lane], g_norm_out[s]);
                }
            }
            float rx = acc.x * ni, ry = acc.y * ni, rz = acc.z * ni, rw = acc.w * ni;
            // split hi / residual lo
            float hx = __bfloat162float(__float2bfloat16(rx));
            float hy = __bfloat162float(__float2bfloat16(ry));
            float hz = __bfloat162float(__float2bfloat16(rz));
            float hw = __bfloat162float(__float2bfloat16(rw));
            uint2 hv, lv;
            hv.x = pack_bf2(rx, ry);
            hv.y = pack_bf2(rz, rw);
            lv.x = pack_bf2(rx - hx, ry - hy);
            lv.y = pack_bf2(rz - hz, rw - hw);
            uint32_t off = tile_off(lr, a_off_col) + (lane & 1) * 8;
            *(uint2*)(smem + SM_AH + off) = hv;
            *(uint2*)(smem + SM_AL + off) = lv;
        }
    }
    __syncthreads();

    // ---- mma phase: 8 warps (2m x 4n), warp tile 32x32 ----
    int wm = wid & 1, wn = wid >> 1;
    int m_base = wm * 32, n_base = wn * 32;

    float acc[2][4][4];
    #pragma unroll
    for (int mt = 0; mt < 2; mt++)
        #pragma unroll
        for (int nt = 0; nt < 4; nt++)
            #pragma unroll
            for (int e = 0; e < 4; e++) acc[mt][nt][e] = 0.0f;

    int arow0 = m_base + (lane & 15);
    int brow  = n_base + (lane & 7);
    uint32_t sa = sb + SM_AH;
    uint32_t sw = sb + SM_WH;

    #pragma unroll
    for (int ks = 0; ks < 8; ks++) {
        int c16a = ks * 2 + (lane >> 4);
        int c16b = ks * 2 + ((lane >> 3) & 1);

        uint32_t ah[2][4], al[2][4];
        #pragma unroll
        for (int mt = 0; mt < 2; mt++) {
            int r = arow0 + mt * 16;
            uint32_t adr = sa + tile_off(r, c16a);
            LDSM4(ah[mt][0], ah[mt][1], ah[mt][2], ah[mt][3], adr);
            LDSM4(al[mt][0], al[mt][1], al[mt][2], al[mt][3], adr + 16384u);
        }
        uint32_t bh[4][2], bl[4][2];
        #pragma unroll
        for (int nt = 0; nt < 4; nt++) {
            int r = brow + nt * 8;
            uint32_t adr = sw + tile_off(r, c16b);
            LDSM2(bh[nt][0], bh[nt][1], adr);
            LDSM2(bl[nt][0], bl[nt][1], adr + 32768u);
        }
        #pragma unroll
        for (int mt = 0; mt < 2; mt++)
            #pragma unroll
            for (int nt = 0; nt < 4; nt++) {
                MMA16816(acc[mt][nt], ah[mt][0], ah[mt][1], ah[mt][2], ah[mt][3],
                         bh[nt][0], bh[nt][1]);
                MMA16816(acc[mt][nt], al[mt][0], al[mt][1], al[mt][2], al[mt][3],
                         bh[nt][0], bh[nt][1]);
                MMA16816(acc[mt][nt], ah[mt][0], ah[mt][1], ah[mt][2], ah[mt][3],
                         bl[nt][0], bl[nt][1]);
            }
    }

    // ---- epilogue: relu(acc + bias) -> dst ----
    int group = lane >> 2, tid4 = lane & 3;
    #pragma unroll
    for (int mt = 0; mt < 2; mt++) {
        #pragma unroll
        for (int nt = 0; nt < 4; nt++) {
            int col = n_base + nt * 8 + tid4 * 2;
            float2 bv = *(const float2*)(bias + col);
            int r1 = row0 + m_base + mt * 16 + group;
            int r2 = r1 + 8;
            float2 v1, v2;
            v1.x = fmaxf(acc[mt][nt][0] + bv.x, 0.f);
            v1.y = fmaxf(acc[mt][nt][1] + bv.y, 0.f);
            v2.x = fmaxf(acc[mt][nt][2] + bv.x, 0.f);
            v2.y = fmaxf(acc[mt][nt][3] + bv.y, 0.f);
            if (!last || r1 < M) *(float2*)(dst + (size_t)r1 * DD + col) = v1;
            if (!last || r2 < M) *(float2*)(dst + (size_t)r2 * DD + col) = v2;
        }
    }
}

// ---------------- colsum over final output + mean ------------------------------
__global__ void __launch_bounds__(256) k_colsum(const float* __restrict__ out, int n) {
    __shared__ float4 s[8][32];
    int tid = threadIdx.x;
    int c = tid & 31;
    int rg = tid >> 5;
    int base = blockIdx.x * 128;
    float4 acc = make_float4(0.f, 0.f, 0.f, 0.f);
    const float4* __restrict__ h4 = (const float4*)out;
    #pragma unroll
    for (int i = 0; i < 16; i++) {
        int r = base + i * 8 + rg;
        if (r < n) acc = f4_add(acc, h4[(size_t)r * 32 + c]);
    }
    s[rg][c] = acc;
    __syncthreads();
    if (rg == 0) {
        float4 t = s[0][c];
        #pragma unroll
        for (int k = 1; k < 8; k++) t = f4_add(t, s[k][c]);
        atomicAdd(&g_colsum[c * 4 + 0], t.x);
        atomicAdd(&g_colsum[c * 4 + 1], t.y);
        atomicAdd(&g_colsum[c * 4 + 2], t.z);
        atomicAdd(&g_colsum[c * 4 + 3], t.w);
    }
}

__global__ void k_mean(float* __restrict__ out_hg, float inv_n) {
    int i = threadIdx.x;
    if (i < DD) out_hg[i] = g_colsum[i] * inv_n;
}

// ---------------- launch ----------------
extern "C" void kernel_launch(void* const* d_in, const int* in_sizes, int n_in,
                              void* d_out, int out_size) {
    const float* feature = (const float*)d_in[0];
    const int*   src     = (const int*)d_in[1];
    const int*   dst     = (const int*)d_in[2];
    const float* W1 = (const float*)d_in[3];
    const float* b1 = (const float*)d_in[4];
    const float* W2 = (const float*)d_in[5];
    const float* b2 = (const float*)d_in[6];
    const float* W3 = (const float*)d_in[7];
    const float* b3 = (const float*)d_in[8];
    float* out = (float*)d_out;

    int N = in_sizes[0] / DD;   // 100000
    int E = in_sizes[1];        // 800000

    int gN     = (N + 255) / 256;
    int gE     = (E + 255) / 256;
    int nchunk = (N + 1023) / 1024;
    int gLayer = NPAD / 64;              // 1564
    int gCs    = (N + 127) / 128;
    int gSplit = (DD * DD + 255) / 256;

    // >48KB dynamic smem (host-side attribute, capture-safe, no alloc)
    cudaFuncSetAttribute(k_layer, cudaFuncAttributeMaxDynamicSharedMemorySize, SM_TOT);

    // preprocessing
    k_zero<<<gN, 256>>>(N);
    k_degrees<<<gE, 256>>>(src, dst, E);
    k_norms<<<gN, 256>>>(N);
    k_scan_partial<<<nchunk, 1024>>>(N);
    k_scan_mid<<<1, 1>>>(nchunk, N);
    k_scan_final<<<nchunk, 1024>>>(N);
    k_csr_fill<<<gE, 256>>>(src, dst, E);

    // weight split + transpose
    k_split_w<<<gSplit, 256>>>(W1, 0);
    k_split_w<<<gSplit, 256>>>(W2, 1);
    k_split_w<<<gSplit, 256>>>(W3, 2);

    // fused layers (ping-pong hidden buffers: feature->g_h0->g_h1->out)
    k_layer<<<gLayer, 256, SM_TOT>>>((const float4*)feature, 0, b1, nullptr, 0, N);
    k_layer<<<gLayer, 256, SM_TOT>>>(nullptr, 1, b2, nullptr, 0, N);
    k_layer<<<gLayer, 256, SM_TOT>>>(nullptr, 2, b3, out, 1, N);

    // readout
    k_colsum<<<gCs, 256>>>(out, N);
    if (out_size >= N * DD + DD) {
        k_mean<<<1, 128>>>(out + (size_t)N * DD, 1.0f / (float)N);
    }
}